// round 11
// baseline (speedup 1.0000x reference)
#include <cuda_runtime.h>
#include <cstdint>

#define TP 132     // 128-wide tile pitch (words)
#define VP 68      // 64-wide tile pitch (words)

typedef unsigned long long u64t;

// ---------------- packed f32x2 helpers (FFMA2 path, sm_103a) ----------------
__device__ __forceinline__ u64t pk2(float x, float y) {
    u64t r; asm("mov.b64 %0, {%1,%2};" : "=l"(r) : "f"(x), "f"(y)); return r;
}
__device__ __forceinline__ u64t ffma2(u64t a, u64t b, u64t c) {
    u64t d; asm("fma.rn.f32x2 %0, %1, %2, %3;" : "=l"(d) : "l"(a), "l"(b), "l"(c)); return d;
}
__device__ __forceinline__ u64t mul2(u64t a, u64t b) {
    u64t d; asm("mul.rn.f32x2 %0, %1, %2;" : "=l"(d) : "l"(a), "l"(b)); return d;
}
__device__ __forceinline__ void upk2(u64t v, float& x, float& y) {
    asm("mov.b64 {%0,%1}, %2;" : "=f"(x), "=f"(y) : "l"(v));
}

// ---------------- tf32 helpers (mma.sync path, sm_80+ so plain sm_103 OK) ----------------
__device__ __forceinline__ uint32_t tf32b(float a) {
    uint32_t u; asm("cvt.rna.tf32.f32 %0, %1;" : "=r"(u) : "f"(a)); return u;
}
__device__ __forceinline__ void cvt_hl(float x, float& h, float& l) {
    uint32_t hb = tf32b(x);
    h = __uint_as_float(hb);
    l = __uint_as_float(tf32b(x - h));
}
__device__ __forceinline__ void mma_tf32(float* d, uint4 a, uint2 b) {
    asm("mma.sync.aligned.m16n8k8.row.col.f32.tf32.tf32.f32 "
        "{%0,%1,%2,%3}, {%4,%5,%6,%7}, {%8,%9}, {%0,%1,%2,%3};"
        : "+f"(d[0]), "+f"(d[1]), "+f"(d[2]), "+f"(d[3])
        : "r"(a.x), "r"(a.y), "r"(a.z), "r"(a.w), "r"(b.x), "r"(b.y));
}

// ---------------- scratch (device globals; no allocation allowed) ----------------
__device__ float g_Y[8192ULL * 2304];      // QKV output (B*N, 3*H*d): t*768 + h*64 + d
__device__ float g_qgr[384ULL * 256 * 64]; // Q-grassmann  [slab][n][d], slab = b*12+h
__device__ float g_kgr[384ULL * 256 * 64];
__device__ float g_attn[384ULL * 256 * 256]; // dots^2*scale, then (in-place) softmaxed attn
__device__ float g_ao[8192ULL * 768];      // attn@V, (b,n,h,d) flattened

// =============== gemm_mma: C = A @ B^T + bias via mma.sync 3xTF32, fragment-order smem ======
// Buffer layout (floats): AH[2048] AL[2048] BH[2048] BL[2048] = 8192 floats/buffer, 2 buffers.
// AH block (s*8+mb): 32 lanes x float4  (a0..a3 fragment of m16k8 tile mb, k8-step s)
// BH block (s*16+nb): 32 lanes x float2 (b0..b1 fragment of n8k8 tile nb)
#define FRAG_BUF 8192

__global__ __launch_bounds__(256, 2) void gemm_mma(const float* __restrict__ A,
                                                   const float* __restrict__ B,
                                                   const float* __restrict__ bias,
                                                   float* __restrict__ C,
                                                   int M, int N, int K)
{
    extern __shared__ float fr[];
    const int n0 = blockIdx.x * 128;
    const int m0 = blockIdx.y * 128;
    const int t  = threadIdx.x;
    const int w  = t >> 5, lane = t & 31;
    const int qg = lane >> 2, qk = lane & 3;
    const int wmB = (w & 1) * 4;      // m16-block base (warp M offset /16)
    const int wnB = (w >> 1) * 4;     // n8-block base  (warp N offset /8)
    // staging mapping: thread -> row lr, k-octet lk
    const int lr = t >> 1, lk = (t & 1) * 8;
    const int sblk = lk >> 3;
    const float* Ap = A + (size_t)(m0 + lr) * K + lk;
    const float* Bp = B + (size_t)(n0 + lr) * K + lk;
    const int mm = lr & 15;
    const int abase = (sblk * 8 + (lr >> 4)) * 128 + (mm & 7) * 16 + (mm >> 3);
    const int bbase = (sblk * 16 + (lr >> 3)) * 64 + (lr & 7) * 8;

    float acc[4][4][4] = {};
    float4 a0, a1, b0, b1;

#define GM_LDG(k0)                                                                                 \
    a0 = *(const float4*)(Ap + (k0));     a1 = *(const float4*)(Ap + (k0) + 4);                    \
    b0 = *(const float4*)(Bp + (k0));     b1 = *(const float4*)(Bp + (k0) + 4);

#define GM_STAGE(Fb) do {                                                                          \
    float va[8] = {a0.x, a0.y, a0.z, a0.w, a1.x, a1.y, a1.z, a1.w};                                \
    float vb[8] = {b0.x, b0.y, b0.z, b0.w, b1.x, b1.y, b1.z, b1.w};                                \
    _Pragma("unroll")                                                                              \
    for (int c = 0; c < 8; ++c) {                                                                  \
        float h, l;                                                                                \
        int oa = abase + (c & 3) * 4 + ((c >> 2) << 1);                                            \
        cvt_hl(va[c], h, l);                                                                       \
        (Fb)[oa] = h; (Fb)[2048 + oa] = l;                                                         \
        int ob = bbase + (c & 3) * 2 + (c >> 2);                                                   \
        cvt_hl(vb[c], h, l);                                                                       \
        (Fb)[4096 + ob] = h; (Fb)[6144 + ob] = l;                                                  \
    }                                                                                              \
} while (0)

#define GM_COMP(Fb, s) do {                                                                        \
    uint2 bhi[4], blo[4];                                                                          \
    _Pragma("unroll")                                                                              \
    for (int j = 0; j < 4; ++j) {                                                                  \
        bhi[j] = *(const uint2*)((Fb) + 4096 + ((s) * 16 + wnB + j) * 64 + lane * 2);              \
        blo[j] = *(const uint2*)((Fb) + 6144 + ((s) * 16 + wnB + j) * 64 + lane * 2);              \
    }                                                                                              \
    _Pragma("unroll")                                                                              \
    for (int i = 0; i < 4; ++i) {                                                                  \
        uint4 ahi = *(const uint4*)((Fb) + ((s) * 8 + wmB + i) * 128 + lane * 4);                  \
        uint4 alo = *(const uint4*)((Fb) + 2048 + ((s) * 8 + wmB + i) * 128 + lane * 4);           \
        _Pragma("unroll")                                                                          \
        for (int j = 0; j < 4; ++j) {                                                              \
            mma_tf32(acc[i][j], ahi, bhi[j]);                                                      \
            mma_tf32(acc[i][j], ahi, blo[j]);                                                      \
            mma_tf32(acc[i][j], alo, bhi[j]);                                                      \
        }                                                                                          \
    }                                                                                              \
} while (0)

    GM_LDG(0)
    GM_STAGE(fr);
    __syncthreads();
    int buf = 0;
    for (int k0 = 16; k0 < K; k0 += 16) {
        GM_LDG(k0)
        { const float* Fb = fr + buf * FRAG_BUF; GM_COMP(Fb, 0); GM_COMP(Fb, 1); }
        { float* Fb = fr + (buf ^ 1) * FRAG_BUF; GM_STAGE(Fb); }
        __syncthreads();
        buf ^= 1;
    }
    { const float* Fb = fr + buf * FRAG_BUF; GM_COMP(Fb, 0); GM_COMP(Fb, 1); }

    // epilogue: acc[i][j]: rows m0+(w&1)*64+16i+{qg,qg+8}, cols n0+(w>>1)*32+8j+2qk..+1
#pragma unroll
    for (int j = 0; j < 4; ++j) {
        const int c = n0 + (w >> 1) * 32 + 8 * j + 2 * qk;
        float2 bb = *(const float2*)(bias + c);
#pragma unroll
        for (int i = 0; i < 4; ++i) {
            const int r0 = m0 + (w & 1) * 64 + 16 * i + qg;
            float2 o0, o1;
            o0.x = acc[i][j][0] + bb.x; o0.y = acc[i][j][1] + bb.y;
            o1.x = acc[i][j][2] + bb.x; o1.y = acc[i][j][3] + bb.y;
            *(float2*)(C + (size_t)r0 * N + c)       = o0;
            *(float2*)(C + (size_t)(r0 + 8) * N + c) = o1;
        }
    }
#undef GM_LDG
#undef GM_STAGE
#undef GM_COMP
}

// ---------------- per-slab dots = Qgr @ Kgr^T, fused square * scale (FFMA2) ----------------
#define G128_LDG()                                                                                 \
    a0 = *(const float4*)(Ap + k0);     a1 = *(const float4*)(Ap + k0 + 4);                        \
    b0 = *(const float4*)(Bp + k0);     b1 = *(const float4*)(Bp + k0 + 4);

#define G128_STORE(Ad, Bd)                                                                         \
    Ad[(lk + 0) * TP + lr] = a0.x; Ad[(lk + 1) * TP + lr] = a0.y;                                  \
    Ad[(lk + 2) * TP + lr] = a0.z; Ad[(lk + 3) * TP + lr] = a0.w;                                  \
    Ad[(lk + 4) * TP + lr] = a1.x; Ad[(lk + 5) * TP + lr] = a1.y;                                  \
    Ad[(lk + 6) * TP + lr] = a1.z; Ad[(lk + 7) * TP + lr] = a1.w;                                  \
    Bd[(lk + 0) * TP + lr] = b0.x; Bd[(lk + 1) * TP + lr] = b0.y;                                  \
    Bd[(lk + 2) * TP + lr] = b0.z; Bd[(lk + 3) * TP + lr] = b0.w;                                  \
    Bd[(lk + 4) * TP + lr] = b1.x; Bd[(lk + 5) * TP + lr] = b1.y;                                  \
    Bd[(lk + 6) * TP + lr] = b1.z; Bd[(lk + 7) * TP + lr] = b1.w;

#define G128_COMP(Ac, Bc)                                                                          \
    _Pragma("unroll")                                                                              \
    for (int kk = 0; kk < 16; ++kk) {                                                              \
        float4 av0 = *(const float4*)(Ac + kk * TP + ty * 8);                                      \
        float4 av1 = *(const float4*)(Ac + kk * TP + ty * 8 + 4);                                  \
        ulonglong2 bL = *(const ulonglong2*)(Bc + kk * TP + tx * 4);                               \
        ulonglong2 bR = *(const ulonglong2*)(Bc + kk * TP + 64 + tx * 4);                          \
        float ar[8] = {av0.x, av0.y, av0.z, av0.w, av1.x, av1.y, av1.z, av1.w};                    \
        _Pragma("unroll")                                                                          \
        for (int i = 0; i < 8; ++i) {                                                              \
            u64t aa = pk2(ar[i], ar[i]);                                                           \
            acc2[i][0] = ffma2(aa, bL.x, acc2[i][0]);                                              \
            acc2[i][1] = ffma2(aa, bL.y, acc2[i][1]);                                              \
            acc2[i][2] = ffma2(aa, bR.x, acc2[i][2]);                                              \
            acc2[i][3] = ffma2(aa, bR.y, acc2[i][3]);                                              \
        }                                                                                          \
    }

__global__ __launch_bounds__(256, 2) void dots128(const float* __restrict__ Qg,
                                                  const float* __restrict__ Kg,
                                                  float* __restrict__ G,
                                                  const float* __restrict__ scale_p)
{
    __shared__ float As[2][16 * TP];
    __shared__ float Bs[2][16 * TP];
    const int slab = blockIdx.z;
    const int m0 = blockIdx.x * 128;
    const int n0 = blockIdx.y * 128;
    const int t  = threadIdx.x;
    const int tx = t & 15, ty = t >> 4;
    const int lr = t >> 1, lk = (t & 1) * 8;
    const float* Ap = Qg + (size_t)slab * 256 * 64 + (size_t)(n0 + lr) * 64 + lk;
    const float* Bp = Kg + (size_t)slab * 256 * 64 + (size_t)(m0 + lr) * 64 + lk;
    u64t acc2[8][4] = {};
    float4 a0, a1, b0, b1;
    int k0 = 0;
    G128_LDG()
    { float* Ad = As[0]; float* Bd = Bs[0]; G128_STORE(Ad, Bd) }
    __syncthreads();
    int buf = 0;
    for (k0 = 16; k0 < 64; k0 += 16) {
        G128_LDG()
        { const float* Ac = As[buf]; const float* Bc = Bs[buf]; G128_COMP(Ac, Bc) }
        { float* Ad = As[buf ^ 1]; float* Bd = Bs[buf ^ 1]; G128_STORE(Ad, Bd) }
        __syncthreads();
        buf ^= 1;
    }
    { const float* Ac = As[buf]; const float* Bc = Bs[buf]; G128_COMP(Ac, Bc) }

    const float sc = *scale_p;
    const u64t scp = pk2(sc, sc);
#pragma unroll
    for (int i = 0; i < 8; ++i) {
        float* gp = G + ((size_t)slab * 256 + n0 + ty * 8 + i) * 256 + m0 + tx * 4;
        ulonglong2 s0, s1;
        s0.x = mul2(mul2(acc2[i][0], acc2[i][0]), scp);
        s0.y = mul2(mul2(acc2[i][1], acc2[i][1]), scp);
        s1.x = mul2(mul2(acc2[i][2], acc2[i][2]), scp);
        s1.y = mul2(mul2(acc2[i][3], acc2[i][3]), scp);
        *(ulonglong2*)gp        = s0;
        *(ulonglong2*)(gp + 64) = s1;
    }
}

// ---------------- per-slab Householder QR (LAPACK convention), Q via org2r ----------------
__global__ void qr_kernel(const float* __restrict__ Y, float* __restrict__ Qq,
                          float* __restrict__ Qk)
{
    extern __shared__ float A[];   // 64 * 257 floats
    __shared__ float tauv[64];
    __shared__ float red[8];
    __shared__ float s_tau, s_inv;
    const int bid = blockIdx.x;
    const int slab = (bid < 384) ? bid : bid - 384;
    const int coloff = (bid < 384) ? 0 : 768;
    float* Qout = (bid < 384) ? Qq : Qk;
    const int b = slab / 12, h = slab % 12;
    const float* src = Y + (size_t)b * 256 * 2304 + coloff + h * 64;
    const int t = threadIdx.x;
    const int lane = t & 31, wid = t >> 5;

    {   // load 256x64, store transposed (column-major)
        const int rloc = t >> 4, dg = (t & 15) << 2;
#pragma unroll
        for (int it = 0; it < 16; ++it) {
            int n = it * 16 + rloc;
            float4 v = *(const float4*)(src + (size_t)n * 2304 + dg);
            A[(dg + 0) * 257 + n] = v.x;
            A[(dg + 1) * 257 + n] = v.y;
            A[(dg + 2) * 257 + n] = v.z;
            A[(dg + 3) * 257 + n] = v.w;
        }
    }
    __syncthreads();

    // -------- geqf2 (unblocked Householder) --------
    for (int j = 0; j < 64; ++j) {
        float p = 0.f;
        if (t > j) { float x = A[j * 257 + t]; p = x * x; }
#pragma unroll
        for (int o = 16; o; o >>= 1) p += __shfl_xor_sync(0xffffffffu, p, o);
        if (lane == 0) red[wid] = p;
        __syncthreads();
        if (t == 0) {
            float xn2 = red[0] + red[1] + red[2] + red[3] + red[4] + red[5] + red[6] + red[7];
            float alpha = A[j * 257 + j];
            float tau, inv;
            if (xn2 <= 0.f) { tau = 0.f; inv = 0.f; }
            else {
                float nrm  = sqrtf(alpha * alpha + xn2);
                float beta = (alpha >= 0.f) ? -nrm : nrm;  // LAPACK dlarfg sign
                tau = (beta - alpha) / beta;
                inv = 1.f / (alpha - beta);
            }
            tauv[j] = tau; s_tau = tau; s_inv = inv;
        }
        __syncthreads();
        float tau = s_tau;
        if (t > j) A[j * 257 + t] *= s_inv;   // v (v0=1 implicit)
        __syncthreads();
        float vr[8];
#pragma unroll
        for (int r = 0; r < 8; ++r) {
            int i = j + lane + 32 * r;
            vr[r] = (i < 256) ? ((i == j) ? 1.f : A[j * 257 + i]) : 0.f;
        }
        for (int k = j + 1 + wid; k < 64; k += 8) {
            float s = 0.f, ar[8];
#pragma unroll
            for (int r = 0; r < 8; ++r) {
                int i = j + lane + 32 * r;
                ar[r] = (i < 256) ? A[k * 257 + i] : 0.f;
                s += vr[r] * ar[r];
            }
#pragma unroll
            for (int o = 16; o; o >>= 1) s += __shfl_xor_sync(0xffffffffu, s, o);
            float ts = tau * s;
#pragma unroll
            for (int r = 0; r < 8; ++r) {
                int i = j + lane + 32 * r;
                if (i < 256) A[k * 257 + i] = ar[r] - ts * vr[r];
            }
        }
        __syncthreads();
    }

    // -------- org2r: form Q in place (backward accumulation) --------
    for (int j = 63; j >= 0; --j) {
        float tau = tauv[j];
        float vr[8];
#pragma unroll
        for (int r = 0; r < 8; ++r) {
            int i = j + lane + 32 * r;
            vr[r] = (i < 256) ? ((i == j) ? 1.f : A[j * 257 + i]) : 0.f;
        }
        for (int k = j + 1 + wid; k < 64; k += 8) {
            float s = 0.f, ar[8];
#pragma unroll
            for (int r = 0; r < 8; ++r) {
                int i = j + lane + 32 * r;
                ar[r] = (i < 256) ? A[k * 257 + i] : 0.f;
                s += vr[r] * ar[r];
            }
#pragma unroll
            for (int o = 16; o; o >>= 1) s += __shfl_xor_sync(0xffffffffu, s, o);
            float ts = tau * s;
#pragma unroll
            for (int r = 0; r < 8; ++r) {
                int i = j + lane + 32 * r;
                if (i < 256) A[k * 257 + i] = ar[r] - ts * vr[r];
            }
        }
        __syncthreads();
        {
            float val;
            if (t < j)       val = 0.f;
            else if (t == j) val = 1.f - tau;
            else             val = -tau * A[j * 257 + t];
            A[j * 257 + t] = val;
        }
        __syncthreads();
    }

    {   // store Q packed [slab][n][d]
        const int rloc = t >> 4, dg = (t & 15) << 2;
#pragma unroll
        for (int it = 0; it < 16; ++it) {
            int n = it * 16 + rloc;
            float4 v;
            v.x = A[(dg + 0) * 257 + n];
            v.y = A[(dg + 1) * 257 + n];
            v.z = A[(dg + 2) * 257 + n];
            v.w = A[(dg + 3) * 257 + n];
            *(float4*)(Qout + ((size_t)slab * 256 + n) * 64 + dg) = v;
        }
    }
}

// ---------------- cross-head 1x1-conv mix + softmax, in place on G (packed conv) -------------
__global__ void mix_softmax(float* __restrict__ G, const float* __restrict__ cw,
                            const float* __restrict__ cbg)
{
    __shared__ float gsm[12 * 256];
    __shared__ float w2[144];
    __shared__ float cb[12];
    const int n = blockIdx.x, b = blockIdx.y;
    const int t = threadIdx.x;          // 384
    const int lane = t & 31, wo = t >> 5;
    if (t < 144) { int o = t / 12, h = t % 12; w2[t] = cw[o * 24 + h] + cw[o * 24 + 12 + h]; }
    if (t < 12) cb[t] = cbg[t];
    {
        float* dstp = gsm + wo * 256;
        const float* srcp = G + ((size_t)(b * 12 + wo) * 256 + n) * 256;
        *(float4*)(dstp + lane * 4)       = *(const float4*)(srcp + lane * 4);
        *(float4*)(dstp + 128 + lane * 4) = *(const float4*)(srcp + 128 + lane * 4);
    }
    __syncthreads();
    // packed conv: pair p = lane + 32*r covers values 2p, 2p+1
    const u64t cbp = pk2(cb[wo], cb[wo]);
    u64t vals2[4] = {cbp, cbp, cbp, cbp};
#pragma unroll
    for (int h = 0; h < 12; ++h) {
        float wv = w2[wo * 12 + h];
        u64t wp = pk2(wv, wv);
        const float* gh = gsm + h * 256;
#pragma unroll
        for (int r = 0; r < 4; ++r) {
            int p = lane + 32 * r;
            u64t g2 = *(const u64t*)(gh + p * 2);
            vals2[r] = ffma2(wp, g2, vals2[r]);
        }
    }
    float vals[8];
#pragma unroll
    for (int r = 0; r < 4; ++r) upk2(vals2[r], vals[2 * r], vals[2 * r + 1]);
    float mx = -3.4e38f;
#pragma unroll
    for (int r = 0; r < 8; ++r) mx = fmaxf(mx, vals[r]);
#pragma unroll
    for (int o = 16; o; o >>= 1) mx = fmaxf(mx, __shfl_xor_sync(0xffffffffu, mx, o));
    float sum = 0.f;
#pragma unroll
    for (int r = 0; r < 8; ++r) { vals[r] = expf(vals[r] - mx); sum += vals[r]; }
#pragma unroll
    for (int o = 16; o; o >>= 1) sum += __shfl_xor_sync(0xffffffffu, sum, o);
    float inv = 1.f / sum;
    float* dst = G + ((size_t)(b * 12 + wo) * 256 + n) * 256;
#pragma unroll
    for (int r = 0; r < 4; ++r) {
        int p = lane + 32 * r;
        float2 o;
        o.x = vals[2 * r] * inv; o.y = vals[2 * r + 1] * inv;
        *(float2*)(dst + p * 2) = o;
    }
}

// ---------------- out_h = attn @ v  (128x64 tile, 8x4/thread packed, double-buffered) ---------
__global__ __launch_bounds__(256, 2) void attnv128(const float* __restrict__ Attn,
                                                   const float* __restrict__ Y,
                                                   float* __restrict__ AO)
{
    __shared__ float As[2][16 * TP];  // [kk][n-row], transposed attn tile
    __shared__ float Bs[2][16 * VP];  // [kk][d]
    const int slab = blockIdx.y;
    const int b = slab / 12, h = slab % 12;
    const int n0 = blockIdx.x * 128;
    const float* Ap = Attn + (size_t)slab * 256 * 256;
    const float* Vp = Y + (size_t)b * 256 * 2304 + 1536 + h * 64;
    const int t = threadIdx.x;
    const int tx = t & 15, ty = t >> 4;
    const int ar = t >> 2, ag = (t & 3) << 2;   // attn: rows ar, ar+64; cols ag..ag+3
    const int vr = t >> 4, vg = (t & 15) << 2;  // V: row vr; cols vg..vg+3
    u64t acc2[8][2] = {};
    float4 a0, a1, v0;
    int m0 = 0;
    a0 = *(const float4*)(Ap + (size_t)(n0 + ar) * 256 + m0 + ag);
    a1 = *(const float4*)(Ap + (size_t)(n0 + 64 + ar) * 256 + m0 + ag);
    v0 = *(const float4*)(Vp + (size_t)(m0 + vr) * 2304 + vg);
    {
        float* Ad = As[0]; float* Bd = Bs[0];
        Ad[(ag + 0) * TP + ar] = a0.x; Ad[(ag + 1) * TP + ar] = a0.y;
        Ad[(ag + 2) * TP + ar] = a0.z; Ad[(ag + 3) * TP + ar] = a0.w;
        Ad[(ag + 0) * TP + 64 + ar] = a1.x; Ad[(ag + 1) * TP + 64 + ar] = a1.y;
        Ad[(ag + 2) * TP + 64 + ar] = a1.z; Ad[(ag + 3) * TP + 64 + ar] = a1.w;
        *(float4*)(Bd + vr * VP + vg) = v0;
    }
    __syncthreads();
    int buf = 0;
    for (m0 = 16; m0 < 256; m0 += 16) {
        a0 = *(const float4*)(Ap + (size_t)(n0 + ar) * 256 + m0 + ag);
        a1 = *(const float4*)(Ap + (size_t)(n0 + 64 + ar) * 256 + m0 + ag);
        v0 = *(const float4*)(Vp + (size_t)(m0 + vr) * 2304 + vg);
        {
            const float* Ac = As[buf]; const float* Bc = Bs[buf];
#pragma unroll
            for (int kk = 0; kk < 16; ++kk) {
                float4 av0 = *(const float4*)(Ac + kk * TP + ty * 8);
                float4 av1 = *(const float4*)(Ac + kk * TP + ty * 8 + 4);
                ulonglong2 bb = *(const ulonglong2*)(Bc + kk * VP + tx * 4);
                float arr[8] = {av0.x, av0.y, av0.z, av0.w, av1.x, av1.y, av1.z, av1.w};
#pragma unroll
                for (int i = 0; i < 8; ++i) {
                    u64t aa = pk2(arr[i], arr[i]);
                    acc2[i][0] = ffma2(aa, bb.x, acc2[i][0]);
                    acc2[i][1] = ffma2(aa, bb.y, acc2[i][1]);
                }
            }
        }
        {
            float* Ad = As[buf ^ 1]; float* Bd = Bs[buf ^ 1];
            Ad[(ag + 0) * TP + ar] = a0.x; Ad[(ag + 1) * TP + ar] = a0.y;
            Ad[(ag + 2) * TP + ar] = a0.z; Ad[(ag + 3) * TP + ar] = a0.w;
            Ad[(ag + 0) * TP + 64 + ar] = a1.x; Ad[(ag + 1) * TP + 64 + ar] = a1.y;
            Ad[(ag + 2) * TP + 64 + ar] = a1.z; Ad[(ag + 3) * TP + 64 + ar] = a1.w;
            *(float4*)(Bd + vr * VP + vg) = v0;
        }
        __syncthreads();
        buf ^= 1;
    }
    {
        const float* Ac = As[buf]; const float* Bc = Bs[buf];
#pragma unroll
        for (int kk = 0; kk < 16; ++kk) {
            float4 av0 = *(const float4*)(Ac + kk * TP + ty * 8);
            float4 av1 = *(const float4*)(Ac + kk * TP + ty * 8 + 4);
            ulonglong2 bb = *(const ulonglong2*)(Bc + kk * VP + tx * 4);
            float arr[8] = {av0.x, av0.y, av0.z, av0.w, av1.x, av1.y, av1.z, av1.w};
#pragma unroll
            for (int i = 0; i < 8; ++i) {
                u64t aa = pk2(arr[i], arr[i]);
                acc2[i][0] = ffma2(aa, bb.x, acc2[i][0]);
                acc2[i][1] = ffma2(aa, bb.y, acc2[i][1]);
            }
        }
    }
#pragma unroll
    for (int i = 0; i < 8; ++i) {
        ulonglong2 s;
        s.x = acc2[i][0]; s.y = acc2[i][1];
        *(ulonglong2*)(AO + (size_t)(b * 256 + n0 + ty * 8 + i) * 768 + h * 64 + tx * 4) = s;
    }
}

// ---------------- launch ----------------
extern "C" void kernel_launch(void* const* d_in, const int* in_sizes, int n_in,
                              void* d_out, int out_size)
{
    (void)in_sizes; (void)n_in; (void)out_size;
    const float* x    = (const float*)d_in[0];
    const float* qkvw = (const float*)d_in[1];
    const float* qkvb = (const float*)d_in[2];
    const float* gsc  = (const float*)d_in[3];
    const float* cw   = (const float*)d_in[4];
    const float* cb   = (const float*)d_in[5];
    const float* pw   = (const float*)d_in[6];
    const float* pb   = (const float*)d_in[7];
    float* out = (float*)d_out;

    float *Y, *qgr, *kgr, *attn, *ao;
    cudaGetSymbolAddress((void**)&Y, g_Y);
    cudaGetSymbolAddress((void**)&qgr, g_qgr);
    cudaGetSymbolAddress((void**)&kgr, g_kgr);
    cudaGetSymbolAddress((void**)&attn, g_attn);
    cudaGetSymbolAddress((void**)&ao, g_ao);

    cudaFuncSetAttribute(qr_kernel, cudaFuncAttributeMaxDynamicSharedMemorySize, 64 * 257 * 4);
    cudaFuncSetAttribute(gemm_mma, cudaFuncAttributeMaxDynamicSharedMemorySize, 2 * FRAG_BUF * 4);

    // 1) QKV: Y = x @ qkv_w^T + qkv_b   (8192 x 2304, K=768) — mma.sync 3xTF32
    gemm_mma<<<dim3(2304 / 128, 8192 / 128), 256, 2 * FRAG_BUF * 4>>>(x, qkvw, qkvb, Y,
                                                                      8192, 2304, 768);
    // 2) Householder QR per (b,h) slab for q AND k in one launch (768 blocks)
    qr_kernel<<<768, 256, 64 * 257 * 4>>>(Y, qgr, kgr);
    // 3) dots^2 * scale per slab (128x128 tiles)
    dots128<<<dim3(2, 2, 384), 256>>>(qgr, kgr, attn, gsc);
    // 4) cross-head mix + softmax (in place)
    mix_softmax<<<dim3(256, 32), 384>>>(attn, cw, cb);
    // 5) attn @ v  -> (b,n,h*64+d)
    attnv128<<<dim3(2, 384), 256>>>(attn, Y, ao);
    // 6) proj: out = ao @ proj_w^T + proj_b — mma.sync 3xTF32
    gemm_mma<<<dim3(768 / 128, 8192 / 128), 256, 2 * FRAG_BUF * 4>>>(ao, pw, pb, out,
                                                                     8192, 768, 768);
}